// round 4
// baseline (speedup 1.0000x reference)
#include <cuda_runtime.h>

// Problem shape constants (from reference setup_inputs; fixed per dataset).
#define BT 4
#define NV 20000
#define NF 40000
#define S  2048
#define TS 16               // samples per block
#define NVP 20224           // NV padded to 79*256 so the vertex loop has no bounds checks
#define BIGF 3.0e38f        // finite "infinity" sentinel (avoids inf/nan edge cases in fma)

// Scratch (device globals; no allocations allowed)
__device__ int    g_visw[(BT * NV) / 4];   // visibility flags, 1 byte per packed vertex
__device__ int    g_inv[BT];               // per-batch "has at least one invisible vertex"
__device__ int    g_is64;                  // index dtype: 1 if int64, 0 if int32
__device__ float4 g_vpack[BT * NVP];       // packed {x,y,z, vis? |v|^2 : BIGF}
__device__ float  g_partial[BT * S];       // per-sample min*mask

// ---------------------------------------------------------------------------
// K1: zero flags + detect int32 vs int64 index layout.
// faces values are uniform in [0, 20000): if stored as int64, every odd int32
// word is the (zero) high half; if int32, odd words are random nonzero face ids.
// ---------------------------------------------------------------------------
__global__ void k_init(const void* __restrict__ faces) {
    int idx = blockIdx.x * blockDim.x + threadIdx.x;
    if (idx < (BT * NV) / 4) g_visw[idx] = 0;
    if (idx < BT) g_inv[idx] = 0;
    if (blockIdx.x == 79) {   // dedicated detection block (past the zeroing range)
        const int* f32 = (const int*)faces;
        int w = f32[2 * threadIdx.x + 1];
        int any = __syncthreads_or(w != 0);
        if (threadIdx.x == 0) g_is64 = (any == 0) ? 1 : 0;
    }
}

// ---------------------------------------------------------------------------
// K2: visibility scatter. pix_to_face -> faces_packed -> mark 3 vertices.
// Races are benign (all stores write 1).
// ---------------------------------------------------------------------------
__global__ void k_scatter(const void* __restrict__ p2f,
                          const void* __restrict__ faces, int npix) {
    int p = blockIdx.x * blockDim.x + threadIdx.x;
    if (p >= npix) return;
    bool is64 = (g_is64 != 0);
    long long fi = is64 ? ((const long long*)p2f)[p]
                        : (long long)((const int*)p2f)[p];
    if (fi < 0) return;
    int f  = (int)fi;          // < BT*NF = 160000
    int fb = f / NF;           // source batch of the face
    int i0, i1, i2;
    if (is64) {
        const long long* fc = (const long long*)faces;
        i0 = (int)fc[3 * f]; i1 = (int)fc[3 * f + 1]; i2 = (int)fc[3 * f + 2];
    } else {
        const int* fc = (const int*)faces;
        i0 = fc[3 * f]; i1 = fc[3 * f + 1]; i2 = fc[3 * f + 2];
    }
    unsigned char* vis = (unsigned char*)g_visw;
    int off = fb * NV;
    vis[off + i0] = 1;
    vis[off + i1] = 1;
    vis[off + i2] = 1;
}

// ---------------------------------------------------------------------------
// K3: pack vertices as float4 {x,y,z,q}, q = vis ? |v|^2 : BIGF.
// Padding rows (r >= NV) get q = BIGF so the main loop needs no bounds checks.
// Also record per-batch "any invisible" (penalty cap 1000 is a candidate iff so).
// ---------------------------------------------------------------------------
__global__ void k_pack(const float* __restrict__ verts) {
    int idx = blockIdx.x * blockDim.x + threadIdx.x;
    if (idx >= BT * NVP) return;
    int b = idx / NVP;
    int r = idx - b * NVP;
    float4 o = make_float4(0.f, 0.f, 0.f, BIGF);
    if (r < NV) {
        int g = b * NV + r;
        const unsigned char* vis = (const unsigned char*)g_visw;
        unsigned char v = vis[g];
        float x = verts[3 * g + 0];
        float y = verts[3 * g + 1];
        float z = verts[3 * g + 2];
        if (v) {
            o.x = x; o.y = y; o.z = z;
            o.w = x * x + y * y + z * z;
        } else {
            g_inv[b] = 1;   // benign race, same value
        }
    }
    g_vpack[idx] = o;
}

// ---------------------------------------------------------------------------
// K4: main distance-min kernel. One block = (batch, 16 samples).
// Each thread scans a strided vertex subset keeping 16 running minima in regs:
// per pair = 3 FFMA (fma pipe) + 1 FMNMX (alu pipe). |s|^2 added after the min.
// ---------------------------------------------------------------------------
__global__ void __launch_bounds__(256) k_dist(const float4* __restrict__ bds) {
    int batch = blockIdx.y;
    int s0 = blockIdx.x * TS;
    __shared__ float4 ssmp[TS];
    __shared__ float  red[8][TS];
    int tid = threadIdx.x;
    if (tid < TS) ssmp[tid] = bds[batch * S + s0 + tid];
    __syncthreads();

    float nsx[TS], nsy[TS], nsz[TS], mn[TS];
#pragma unroll
    for (int i = 0; i < TS; i++) {
        float4 q = ssmp[i];
        nsx[i] = -2.0f * q.x;
        nsy[i] = -2.0f * q.y;
        nsz[i] = -2.0f * q.z;
        mn[i] = BIGF;
    }

    const float4* vp = g_vpack + batch * NVP;
#pragma unroll 2
    for (int it = 0; it < NVP / 256; ++it) {
        float4 p = vp[it * 256 + tid];
#pragma unroll
        for (int i = 0; i < TS; i++) {
            float t = fmaf(p.x, nsx[i], p.w);
            t = fmaf(p.y, nsy[i], t);
            t = fmaf(p.z, nsz[i], t);
            mn[i] = fminf(mn[i], t);
        }
    }

    // intra-warp min reduction
#pragma unroll
    for (int i = 0; i < TS; i++) {
#pragma unroll
        for (int o = 16; o > 0; o >>= 1)
            mn[i] = fminf(mn[i], __shfl_xor_sync(0xffffffffu, mn[i], o));
    }
    int warp = tid >> 5, lane = tid & 31;
    if (lane == 0) {
#pragma unroll
        for (int i = 0; i < TS; i++) red[warp][i] = mn[i];
    }
    __syncthreads();

    if (tid < TS) {
        float m = red[0][tid];
#pragma unroll
        for (int w = 1; w < 8; w++) m = fminf(m, red[w][tid]);
        float4 q = ssmp[tid];
        float sn = q.x * q.x + q.y * q.y + q.z * q.z;
        float cap = g_inv[batch] ? 1000.0f : BIGF;
        g_partial[batch * S + s0 + tid] = fminf(m + sn, cap) * q.w;
    }
}

// ---------------------------------------------------------------------------
// K5: deterministic fixed-order reduction of the 8192 per-sample values.
// loss = (sum over all batch,sample) / BT
// ---------------------------------------------------------------------------
__global__ void k_reduce(float* __restrict__ out) {
    __shared__ float sd[256];
    int tid = threadIdx.x;
    const int PER = (BT * S) / 256;   // 32
    float acc = 0.f;
#pragma unroll
    for (int j = 0; j < PER; j++) acc += g_partial[tid * PER + j];
    sd[tid] = acc;
    __syncthreads();
    for (int s = 128; s > 0; s >>= 1) {
        if (tid < s) sd[tid] += sd[tid + s];
        __syncthreads();
    }
    if (tid == 0) out[0] = sd[0] * (1.0f / BT);
}

// ---------------------------------------------------------------------------
extern "C" void kernel_launch(void* const* d_in, const int* in_sizes, int n_in,
                              void* d_out, int out_size) {
    const float* verts = (const float*)d_in[0];   // (4,20000,3) f32
    const float* bds   = (const float*)d_in[1];   // (4,2048,4)  f32
    const void*  faces = d_in[2];                 // (4,40000,3) int32 or int64
    const void*  p2f   = d_in[3];                 // (4,256,256,1) int32 or int64
    float* out = (float*)d_out;

    int npix = in_sizes[3];   // BT*H*W

    k_init<<<80, 256>>>(faces);
    k_scatter<<<(npix + 255) / 256, 256>>>(p2f, faces, npix);
    k_pack<<<(BT * NVP + 255) / 256, 256>>>(verts);
    k_dist<<<dim3(S / TS, BT), 256>>>((const float4*)bds);
    k_reduce<<<1, 256>>>(out);
}